// round 17
// baseline (speedup 1.0000x reference)
#include <cuda_runtime.h>
#include <cuda_fp16.h>
#include <stdint.h>
#include <math.h>

#define NN 10000
#define EE 640000
#define F  64
#define EFD 16

typedef unsigned long long u64p;

// ---- scratch (device globals; no allocations allowed) ----
__device__ __half g_Asrc16[NN*F];
__device__ __half g_Adst16[NN*F];
__device__ __half g_Kn16[NN*F];
__device__ __half g_Qn16[NN*F];
__device__ float g_Qk[NN*EFD];
__device__ float g_qd2[NN];
__device__ float g_denom[NN];
__device__ float g_hneigh[NN*F];
__device__ float g_e[EE];      // holds exp(score) after K1
__device__ float g_dist[EE];

__device__ __forceinline__ float siluf(float x) { return x / (1.f + __expf(-x)); }

__device__ __forceinline__ void redAdd4(float* addr, float a, float b, float c, float d) {
    asm volatile("red.global.add.v4.f32 [%0], {%1,%2,%3,%4};"
                 :: "l"(addr), "f"(a), "f"(b), "f"(c), "f"(d) : "memory");
}

__device__ __forceinline__ u64p pack2(float x, float y) {
    u64p r; asm("mov.b64 %0, {%1,%2};" : "=l"(r) : "f"(x), "f"(y)); return r;
}
__device__ __forceinline__ void unpack2(u64p v, float& x, float& y) {
    asm("mov.b64 {%0,%1}, %2;" : "=f"(x), "=f"(y) : "l"(v));
}
__device__ __forceinline__ void ffma2(u64p& d, u64p a, u64p b) {
    asm("fma.rn.f32x2 %0, %1, %2, %0;" : "+l"(d) : "l"(a), "l"(b));
}

__device__ __forceinline__ uint32_t smem_u32(const void* p) {
    uint32_t a;
    asm("{ .reg .u64 t; cvta.to.shared.u64 t, %1; cvt.u32.u64 %0, t; }" : "=r"(a) : "l"(p));
    return a;
}
__device__ __forceinline__ uint32_t swz128(uint32_t x) { return x ^ ((x >> 3) & 0x70u); }
__device__ __forceinline__ uint32_t swz64(uint32_t x)  { return x ^ ((x >> 3) & 0x30u); }

__device__ __forceinline__ void ldmx4(uint32_t& a0, uint32_t& a1, uint32_t& a2, uint32_t& a3,
                                      uint32_t addr) {
    asm volatile("ldmatrix.sync.aligned.m8n8.x4.shared.b16 {%0,%1,%2,%3}, [%4];"
                 : "=r"(a0), "=r"(a1), "=r"(a2), "=r"(a3) : "r"(addr));
}
__device__ __forceinline__ void ldmx2t(uint32_t& b0, uint32_t& b1, uint32_t addr) {
    asm volatile("ldmatrix.sync.aligned.m8n8.x2.trans.shared.b16 {%0,%1}, [%2];"
                 : "=r"(b0), "=r"(b1) : "r"(addr));
}
__device__ __forceinline__ void mma16816(float& d0, float& d1, float& d2, float& d3,
                                         uint32_t a0, uint32_t a1, uint32_t a2, uint32_t a3,
                                         uint32_t b0, uint32_t b1) {
    asm volatile("mma.sync.aligned.m16n8k16.row.col.f32.f16.f16.f32 "
                 "{%0,%1,%2,%3}, {%4,%5,%6,%7}, {%8,%9}, {%0,%1,%2,%3};"
                 : "+f"(d0), "+f"(d1), "+f"(d2), "+f"(d3)
                 : "r"(a0), "r"(a1), "r"(a2), "r"(a3), "r"(b0), "r"(b1));
}

// ================= K0: per-node precompute (fp16 tables) + init =================
__global__ void k0_node_pre(const float* __restrict__ nf,
                            const float* __restrict__ We1,
                            const float* __restrict__ Wk,
                            const float* __restrict__ Wq) {
    __shared__ __align__(16) float srow[4 * F];
    __shared__ __align__(16) float sQ[4 * F];
    int tid = threadIdx.x;
    int nodeBase = blockIdx.x * 4;
    srow[tid] = nf[(size_t)nodeBase * F + tid];
    __syncthreads();
    int ln = tid >> 6;
    int c  = tid & 63;
    int node = nodeBase + ln;
    const float* r = srow + ln * F;
    float a0 = 0.f, a1 = 0.f, a2 = 0.f, a3 = 0.f;
#pragma unroll 8
    for (int k = 0; k < F; ++k) {
        float x = r[k];
        a0 += x * __ldg(We1 + k * F + c);
        a1 += x * __ldg(We1 + (F + k) * F + c);
        a2 += x * __ldg(Wk  + k * F + c);
        a3 += x * __ldg(Wq  + k * F + c);
    }
    g_Asrc16[node * F + c] = __float2half_rn(a0);
    g_Adst16[node * F + c] = __float2half_rn(a1);
    g_Kn16  [node * F + c] = __float2half_rn(a2);
    g_Qn16  [node * F + c] = __float2half_rn(a3);
    sQ[ln * F + c] = a3;
    g_hneigh[node * F + c] = 0.f;
    if (c == 0) g_denom[node] = 0.f;
    __syncthreads();
    if (tid < 64) {
        int ln2 = tid >> 4, j = tid & 15;
        const float* q = sQ + ln2 * F;
        float acc = 0.f;
#pragma unroll 8
        for (int k = 0; k < F; ++k) acc += q[k] * __ldg(Wk + (65 + j) * F + k);
        g_Qk[(nodeBase + ln2) * EFD + j] = acc;
    } else if (tid < 68) {
        int ln2 = tid - 64;
        const float* q = sQ + ln2 * F;
        float acc = 0.f;
#pragma unroll 8
        for (int k = 0; k < F; ++k) acc += q[k] * __ldg(Wk + 64 * F + k);
        g_qd2[nodeBase + ln2] = acc;
    }
}

// ================= K1: edge scores -> exp(e), denom atomicAdd (fp16 gathers) =================
__global__ void __launch_bounds__(256)
k1_scores(const float* __restrict__ coord,
          const float* __restrict__ efeat,
          const int* __restrict__ src,
          const int* __restrict__ dst) {
    int tid = threadIdx.x;
    int warp = tid >> 5, lane = tid & 31;
    int sub = lane >> 4, c = lane & 15;
    int base = blockIdx.x * 128 + warp * 16;

#pragma unroll
    for (int it = 0; it < 8; ++it) {
        int e = base + it * 2 + sub;
        int s = __ldg(&src[e]);
        int d = __ldg(&dst[e]);

        uint2 ku = __ldg((const uint2*)(g_Kn16 + (size_t)s * F) + c);
        uint2 qu = __ldg((const uint2*)(g_Qn16 + (size_t)d * F) + c);
        float2 k0 = __half22float2(*(__half2*)&ku.x);
        float2 k1 = __half22float2(*(__half2*)&ku.y);
        float2 q0 = __half22float2(*(__half2*)&qu.x);
        float2 q1 = __half22float2(*(__half2*)&qu.y);
        float part = k0.x * q0.x + k0.y * q0.y + k1.x * q1.x + k1.y * q1.y;

        if (c < 4) {
            float4 ev = __ldg((const float4*)(efeat + (size_t)e * EFD) + c);
            float4 qk = __ldg((const float4*)(g_Qk + (size_t)d * EFD) + c);
            part += ev.x * qk.x + ev.y * qk.y + ev.z * qk.z + ev.w * qk.w;
        }

        float dist = 0.f;
        if (c == 0) {
            float dx = __ldg(&coord[s * 3 + 0]) - __ldg(&coord[d * 3 + 0]);
            float dy = __ldg(&coord[s * 3 + 1]) - __ldg(&coord[d * 3 + 1]);
            float dz = __ldg(&coord[s * 3 + 2]) - __ldg(&coord[d * 3 + 2]);
            dist = sqrtf(dx * dx + dy * dy + dz * dz);
            part += dist * __ldg(&g_qd2[d]);
        }

#pragma unroll
        for (int o = 8; o; o >>= 1)
            part += __shfl_down_sync(0xffffffffu, part, o, 16);

        if (c == 0) {
            float v = __expf(part * 0.125f);
            g_e[e] = v;
            g_dist[e] = dist;
            atomicAdd(&g_denom[d], v);
        }
    }
}

// ================= K3: dual mma.sync edge message + scatter, 256 edges/block =================
// 512 threads, 68.3KB smem -> 2 blocks/SM (32 warps).
// byte layout:
//   [0,32768)      A-tile fp16 [256e][64h], SW128 (gather writes pre; Phase A RMW -> h1)
//   [32768,40960)  B-tile fp16 [64h][64c], SW128 (We2)
//   [40960,45056)  Wa fp16 [32k][64h], SW128
//   [45056,61440)  efx fp16 [256e][32k], 64B rows SW64
//   epilogue SCR [16 c4][1028] fl overlays bytes [0,65792)
//   floats >= 16448: att[256], dst[256], b1[64], b2[64]
#define EPB 256
#define GSTRIDE 1028
#define SM_B_BYTE   32768
#define SM_WA_BYTE  40960
#define SM_EFX_BYTE 45056
#define SM_ATT_FLT  16448
#define SM_DST_FLT  16704
#define SM_B1_FLT   16960
#define SM_B2_FLT   17024
#define SM_FLOATS   17088

__global__ void __launch_bounds__(512, 2)
k3_message(const float* __restrict__ efeat,
           const float* __restrict__ We1,
           const float* __restrict__ be1,
           const float* __restrict__ We2,
           const float* __restrict__ be2,
           const int* __restrict__ src,
           const int* __restrict__ dst) {
    extern __shared__ __align__(1024) float sm[];
    char* smb = (char*)sm;
    float* sAtt  = sm + SM_ATT_FLT;
    int*   sDstA = (int*)(sm + SM_DST_FLT);
    float* sB1   = sm + SM_B1_FLT;
    float* sB2   = sm + SM_B2_FLT;

    int tid = threadIdx.x;
    int lane = tid & 31;
    int wid = tid >> 5;
    int blockbase = blockIdx.x * EPB;
    uint32_t sbase = smem_u32(sm);

    // ---- stage Wa fp16 [32k][64h]: k0-15 = We1[129+k], k16 = We1[128], rest 0 ----
#pragma unroll
    for (int it = 0; it < 4; ++it) {
        int i = it * 512 + tid;      // 0..2047
        int k = i >> 6, h = i & 63;
        float v = (k < 16) ? We1[(129 + k) * F + h]
                           : (k == 16 ? We1[128 * F + h] : 0.f);
        *(__half*)(smb + SM_WA_BYTE + swz128((uint32_t)(k * 128 + h * 2))) =
            __float2half_rn(v);
    }
    if (tid >= 256 && tid < 320) sB1[tid - 256] = be1[tid - 256];
    else if (tid >= 320 && tid < 384) sB2[tid - 320] = be2[tid - 320];
    // ---- per-edge scalars + efx upper half-row (k16 = dist, k17-31 = 0) ----
    if (tid < 256) {
        int e = blockbase + tid;
        int d = __ldg(&dst[e]);
        sDstA[tid] = d;
        sAtt[tid] = __fdividef(__ldg(&g_e[e]), __ldg(&g_denom[d]));
        float dist = __ldg(&g_dist[e]);
        __half2 dz = __floats2half2_rn(dist, 0.f);
        uint4 u0;
        u0.x = *(uint32_t*)&dz; u0.y = 0; u0.z = 0; u0.w = 0;
        *(uint4*)(smb + SM_EFX_BYTE + swz64((uint32_t)(tid * 64 + 32))) = u0;
        uint4 z; z.x = z.y = z.z = z.w = 0;
        *(uint4*)(smb + SM_EFX_BYTE + swz64((uint32_t)(tid * 64 + 48))) = z;
    }
    // ---- efx lower half: k0-15 = efeat fp16 ----
#pragma unroll
    for (int it = 0; it < 2; ++it) {
        int item = it * 512 + tid;   // 0..1023
        int e = item >> 2;
        int c = item & 3;
        float4 v = __ldg((const float4*)(efeat + (size_t)(blockbase + e) * EFD) + c);
        __half2 h0 = __floats2half2_rn(v.x, v.y);
        __half2 h1 = __floats2half2_rn(v.z, v.w);
        uint2 u;
        u.x = *(uint32_t*)&h0;
        u.y = *(uint32_t*)&h1;
        *(uint2*)(smb + SM_EFX_BYTE + swz64((uint32_t)(e * 64 + c * 8))) = u;
    }
    // ---- stage B-tile: We2 [h][c] fp16, SW128 ----
#pragma unroll
    for (int it = 0; it < 8; ++it) {
        int i = it * 512 + tid;      // 0..4095
        int h = i >> 6, c = i & 63;
        *(__half*)(smb + SM_B_BYTE + swz128((uint32_t)(h * 128 + c * 2))) =
            __float2half_rn(We2[h * F + c]);
    }
    // ---- coalesced fp16 gather of pre = Asrc[s]+Adst[d] into A-tile ----
#pragma unroll
    for (int it = 0; it < 8; ++it) {
        int item = it * 512 + tid;   // 0..4095
        int e = item >> 4;
        int c = item & 15;           // 4-h group
        int s = __ldg(&src[blockbase + e]);
        int d = __ldg(&dst[blockbase + e]);
        uint2 ua = __ldg((const uint2*)(g_Asrc16 + (size_t)s * F) + c);
        uint2 ub = __ldg((const uint2*)(g_Adst16 + (size_t)d * F) + c);
        __half2 s0 = __hadd2(*(__half2*)&ua.x, *(__half2*)&ub.x);
        __half2 s1 = __hadd2(*(__half2*)&ua.y, *(__half2*)&ub.y);
        uint2 u;
        u.x = *(uint32_t*)&s0;
        u.y = *(uint32_t*)&s1;
        *(uint2*)(smb + swz128((uint32_t)(e * 128 + c * 8))) = u;
    }
    __syncthreads();

    int ew = wid * 16;   // 16 warps x 16 edges = 256

    // ---------------- Phase A: mma.sync, warp = 16e x 64h, K=32 ----------------
    {
        float pacc[8][4];
#pragma unroll
        for (int j = 0; j < 8; ++j)
            pacc[j][0] = pacc[j][1] = pacc[j][2] = pacc[j][3] = 0.f;

        uint32_t arow = (uint32_t)((ew + (lane & 15)) * 64) + ((lane >> 4) << 4);
        uint32_t brow = (uint32_t)((lane & 15) * 128);
#pragma unroll
        for (int kk = 0; kk < 2; ++kk) {
            uint32_t a0, a1, a2, a3;
            ldmx4(a0, a1, a2, a3, sbase + SM_EFX_BYTE + swz64(arow + kk * 32));
#pragma unroll
            for (int j = 0; j < 8; ++j) {
                uint32_t b0, b1;
                ldmx2t(b0, b1, sbase + SM_WA_BYTE + swz128(brow + kk * 16 * 128 + j * 16));
                mma16816(pacc[j][0], pacc[j][1], pacc[j][2], pacc[j][3],
                         a0, a1, a2, a3, b0, b1);
            }
        }

        // h1 = silu(pre + b1 + acc), RMW in A-tile at D-fragment coords
        int g = lane >> 2, tg = lane & 3;
        int r0 = ew + g, r1 = r0 + 8;
#pragma unroll
        for (int j = 0; j < 8; ++j) {
            int c = j * 8 + tg * 2;
            float b1a = sB1[c], b1b = sB1[c + 1];
            char* p0 = smb + swz128((uint32_t)(r0 * 128 + c * 2));
            char* p1 = smb + swz128((uint32_t)(r1 * 128 + c * 2));
            float2 f0 = __half22float2(*(__half2*)p0);
            float2 f1 = __half22float2(*(__half2*)p1);
            __half2 o0 = __floats2half2_rn(siluf(f0.x + pacc[j][0] + b1a),
                                           siluf(f0.y + pacc[j][1] + b1b));
            __half2 o1 = __floats2half2_rn(siluf(f1.x + pacc[j][2] + b1a),
                                           siluf(f1.y + pacc[j][3] + b1b));
            *(__half2*)p0 = o0;
            *(__half2*)p1 = o1;
        }
    }
    __syncthreads();

    // ---------------- Phase B: mma.sync, warp = 16e x 64c ----------------
    float acc[8][4];
#pragma unroll
    for (int j = 0; j < 8; ++j)
        acc[j][0] = acc[j][1] = acc[j][2] = acc[j][3] = 0.f;

    {
        uint32_t arow = (uint32_t)((ew + (lane & 15)) * 128) + ((lane >> 4) << 4);
        uint32_t brow = (uint32_t)((lane & 15) * 128);
#pragma unroll
        for (int kk = 0; kk < 4; ++kk) {
            uint32_t a0, a1, a2, a3;
            ldmx4(a0, a1, a2, a3, sbase + swz128(arow + kk * 32));
#pragma unroll
            for (int j = 0; j < 8; ++j) {
                uint32_t b0, b1;
                ldmx2t(b0, b1, sbase + SM_B_BYTE + swz128(brow + kk * 16 * 128 + j * 16));
                mma16816(acc[j][0], acc[j][1], acc[j][2], acc[j][3],
                         a0, a1, a2, a3, b0, b1);
            }
        }
    }
    __syncthreads();   // A/B tiles dead; epilogue overlays them

    // ---- epilogue: silu(d + b2) * att into SCR [c4][e][4] ----
    {
        int g = lane >> 2;
        int tg = lane & 3;
        int r0 = ew + g, r1 = r0 + 8;
        float att0 = sAtt[r0], att1 = sAtt[r1];
#pragma unroll
        for (int j = 0; j < 8; ++j) {
            int c = j * 8 + tg * 2;
            float b2a = sB2[c], b2b = sB2[c + 1];
            float* base = sm + (c >> 2) * GSTRIDE + (c & 3);
            *(float2*)(base + r0 * 4) =
                make_float2(siluf(acc[j][0] + b2a) * att0, siluf(acc[j][1] + b2b) * att0);
            *(float2*)(base + r1 * 4) =
                make_float2(siluf(acc[j][2] + b2a) * att1, siluf(acc[j][3] + b2b) * att1);
        }
    }
    __syncthreads();

    // ---- coalesced REDG scatter ----
#pragma unroll
    for (int it = 0; it < 8; ++it) {
        int item = it * 512 + tid;   // 0..4095
        int e = item >> 4;
        int c = item & 15;
        float4 v = *(const float4*)(sm + c * GSTRIDE + e * 4);
        redAdd4(g_hneigh + (size_t)sDstA[e] * F + c * 4, v.x, v.y, v.z, v.w);
    }
}

// ================= K4: node MLP — FFMA2, 4 ch x 2 nodes per thread, 32 nodes/block =================
__global__ void __launch_bounds__(256)
k4_node(const float* __restrict__ nf,
        const float* __restrict__ Wn1,
        const float* __restrict__ bn1,
        const float* __restrict__ Wn2,
        const float* __restrict__ bn2,
        float* __restrict__ out) {
    __shared__ __align__(16) float sIn[32 * 132];
    __shared__ __align__(16) float sH1[32 * 68];
    int tid = threadIdx.x;
    int nodeBase = blockIdx.x * 32;

#pragma unroll
    for (int it = 0; it < 4; ++it) {
        int item = it * 256 + tid;   // 0..1023
        int n = item >> 5;
        int q = item & 31;
        int node = nodeBase + n;
        float4 v = make_float4(0.f, 0.f, 0.f, 0.f);
        if (node < NN)
            v = (q < 16)
                ? __ldg((const float4*)(nf + (size_t)node * F) + q)
                : *(const float4*)(g_hneigh + (size_t)node * F + (q - 16) * 4);
        *(float4*)(sIn + n * 132 + q * 4) = v;
    }
    __syncthreads();

    int ng = tid >> 4;          // node pair 0..15
    int cq = (tid & 15) * 4;    // channels cq..cq+3
    int n0 = ng * 2, n1 = n0 + 1;
    const float* x0 = sIn + n0 * 132;
    const float* x1 = sIn + n1 * 132;

    u64p a00, a01, a10, a11;
    {
        float4 b = __ldg((const float4*)(bn1 + cq));
        a00 = pack2(b.x, b.y); a01 = pack2(b.z, b.w);
        a10 = a00; a11 = a01;
    }
#pragma unroll 8
    for (int k = 0; k < 128; ++k) {
        ulonglong2 w = __ldg((const ulonglong2*)(Wn1 + k * F + cq));
        u64p p0 = pack2(x0[k], x0[k]);
        u64p p1 = pack2(x1[k], x1[k]);
        ffma2(a00, p0, w.x); ffma2(a01, p0, w.y);
        ffma2(a10, p1, w.x); ffma2(a11, p1, w.y);
    }
    {
        float v0, v1, v2, v3;
        unpack2(a00, v0, v1); unpack2(a01, v2, v3);
        *(float4*)(sH1 + n0 * 68 + cq) =
            make_float4(siluf(v0), siluf(v1), siluf(v2), siluf(v3));
        unpack2(a10, v0, v1); unpack2(a11, v2, v3);
        *(float4*)(sH1 + n1 * 68 + cq) =
            make_float4(siluf(v0), siluf(v1), siluf(v2), siluf(v3));
    }
    __syncthreads();

    const float* h0 = sH1 + n0 * 68;
    const float* h1 = sH1 + n1 * 68;
    {
        float4 b = __ldg((const float4*)(bn2 + cq));
        a00 = pack2(b.x, b.y); a01 = pack2(b.z, b.w);
        a10 = a00; a11 = a01;
    }
#pragma unroll 8
    for (int k = 0; k < 64; ++k) {
        ulonglong2 w = __ldg((const ulonglong2*)(Wn2 + k * F + cq));
        u64p p0 = pack2(h0[k], h0[k]);
        u64p p1 = pack2(h1[k], h1[k]);
        ffma2(a00, p0, w.x); ffma2(a01, p0, w.y);
        ffma2(a10, p1, w.x); ffma2(a11, p1, w.y);
    }
    float v0, v1, v2, v3;
    if (nodeBase + n0 < NN) {
        unpack2(a00, v0, v1); unpack2(a01, v2, v3);
        *(float4*)(out + (size_t)(nodeBase + n0) * F + cq) = make_float4(v0, v1, v2, v3);
    }
    if (nodeBase + n1 < NN) {
        unpack2(a10, v0, v1); unpack2(a11, v2, v3);
        *(float4*)(out + (size_t)(nodeBase + n1) * F + cq) = make_float4(v0, v1, v2, v3);
    }
}

extern "C" void kernel_launch(void* const* d_in, const int* in_sizes, int n_in,
                              void* d_out, int out_size) {
    const float* nf    = (const float*)d_in[0];
    const float* coord = (const float*)d_in[1];
    const float* efeat = (const float*)d_in[2];
    const float* We1   = (const float*)d_in[3];
    const float* be1   = (const float*)d_in[4];
    const float* We2   = (const float*)d_in[5];
    const float* be2   = (const float*)d_in[6];
    const float* Wn1   = (const float*)d_in[7];
    const float* bn1   = (const float*)d_in[8];
    const float* Wn2   = (const float*)d_in[9];
    const float* bn2   = (const float*)d_in[10];
    const float* Wq    = (const float*)d_in[11];
    const float* Wk    = (const float*)d_in[12];
    const int*   src   = (const int*)d_in[13];
    const int*   dst   = (const int*)d_in[14];
    float* out = (float*)d_out;

    const int k3_smem = SM_FLOATS * (int)sizeof(float);
    cudaFuncSetAttribute(k3_message, cudaFuncAttributeMaxDynamicSharedMemorySize, k3_smem);

    k0_node_pre<<<NN / 4, 256>>>(nf, We1, Wk, Wq);
    k1_scores<<<EE / 128, 256>>>(coord, efeat, src, dst);
    k3_message<<<EE / EPB, 512, k3_smem>>>(efeat, We1, be1, We2, be2, src, dst);
    k4_node<<<(NN + 31) / 32, 256>>>(nf, Wn1, bn1, Wn2, bn2, out);
}